// round 6
// baseline (speedup 1.0000x reference)
#include <cuda_runtime.h>

// Lower-triangular matvec: y[i] = sum_{j<=i} W[i,j] * x[j]
// n = 8192, W row-major fp32 (lower triangle = 128 MB, streamed once).
//
// R6: pair-block layout (block b -> rows b and n-1-b, exactly n+1 elements
// per block). Two changes vs R2 (29.2us, DRAM 62.6%):
//  (a) x is hoisted into 8 float4 REGISTERS per thread once; thread tid only
//      ever touches k = tid + 256u (u<8, max 2047 < n/4) for BOTH rows, so
//      zero x-loads in the hot path.
//  (b) W is loaded as one 8-deep predicated LDG.128 batch per row, then
//      consumed -- doubling average outstanding loads per warp.

#define NTHREADS 256

__device__ __forceinline__ float dot4(float4 w, float4 v) {
    return w.x * v.x + w.y * v.y + w.z * v.z + w.w * v.w;
}

__global__ __launch_bounds__(NTHREADS)
void tril_mv_kernel(const float* __restrict__ x,
                    const float* __restrict__ W,
                    float* __restrict__ y,
                    int n)
{
    __shared__ float red0[NTHREADS / 32];
    __shared__ float red1[NTHREADS / 32];

    const int b   = blockIdx.x;       // 0 .. n/2-1
    const int tid = threadIdx.x;

    const int r0 = b;
    const int r1 = n - 1 - b;

    // --- hoist x: thread tid covers k = tid + 256u, u = 0..7 (k <= 2047) ---
    const float4* __restrict__ x4 = reinterpret_cast<const float4*>(x);
    float4 xv[8];
    #pragma unroll
    for (int u = 0; u < 8; u++) {
        xv[u] = __ldg(x4 + tid + u * NTHREADS);
    }

    float acc0, acc1;

    // --- row r0 (length r0+1): 8-deep predicated W batch ---
    {
        const int m = (r0 + 1) >> 2;        // float4 count
        const float4* __restrict__ W4 =
            reinterpret_cast<const float4*>(W + (size_t)r0 * n);
        float4 w[8];
        #pragma unroll
        for (int u = 0; u < 8; u++) {
            const int k = tid + u * NTHREADS;
            if (k < m) w[u] = __ldcs(W4 + k);
        }
        float a0 = 0.f, a1 = 0.f, a2 = 0.f, a3 = 0.f;
        #pragma unroll
        for (int u = 0; u < 8; u++) {
            const int k = tid + u * NTHREADS;
            float p = (k < m) ? dot4(w[u], xv[u]) : 0.0f;
            if      ((u & 3) == 0) a0 += p;
            else if ((u & 3) == 1) a1 += p;
            else if ((u & 3) == 2) a2 += p;
            else                   a3 += p;
        }
        acc0 = (a0 + a1) + (a2 + a3);
        // scalar tail (len % 4)
        const int tail = (r0 + 1) & 3;
        if (tid < tail) {
            const int j = (m << 2) + tid;
            acc0 += W[(size_t)r0 * n + j] * x[j];
        }
    }

    // --- row r1 (length r1+1): 8-deep predicated W batch ---
    {
        const int m = (r1 + 1) >> 2;
        const float4* __restrict__ W4 =
            reinterpret_cast<const float4*>(W + (size_t)r1 * n);
        float4 w[8];
        #pragma unroll
        for (int u = 0; u < 8; u++) {
            const int k = tid + u * NTHREADS;
            if (k < m) w[u] = __ldcs(W4 + k);
        }
        float a0 = 0.f, a1 = 0.f, a2 = 0.f, a3 = 0.f;
        #pragma unroll
        for (int u = 0; u < 8; u++) {
            const int k = tid + u * NTHREADS;
            float p = (k < m) ? dot4(w[u], xv[u]) : 0.0f;
            if      ((u & 3) == 0) a0 += p;
            else if ((u & 3) == 1) a1 += p;
            else if ((u & 3) == 2) a2 += p;
            else                   a3 += p;
        }
        acc1 = (a0 + a1) + (a2 + a3);
        const int tail = (r1 + 1) & 3;
        if (tid < tail) {
            const int j = (m << 2) + tid;
            acc1 += W[(size_t)r1 * n + j] * x[j];
        }
    }

    // ---- dual block reduction ----
    #pragma unroll
    for (int off = 16; off > 0; off >>= 1) {
        acc0 += __shfl_down_sync(0xffffffffu, acc0, off);
        acc1 += __shfl_down_sync(0xffffffffu, acc1, off);
    }
    const int warp = tid >> 5;
    const int lane = tid & 31;
    if (lane == 0) {
        red0[warp] = acc0;
        red1[warp] = acc1;
    }
    __syncthreads();

    if (warp == 0) {
        float a0 = (lane < NTHREADS / 32) ? red0[lane] : 0.0f;
        float a1 = (lane < NTHREADS / 32) ? red1[lane] : 0.0f;
        #pragma unroll
        for (int off = (NTHREADS / 64); off > 0; off >>= 1) {
            a0 += __shfl_down_sync(0xffffffffu, a0, off);
            a1 += __shfl_down_sync(0xffffffffu, a1, off);
        }
        if (lane == 0) {
            y[r0] = a0;
            y[r1] = a1;
        }
    }
}

extern "C" void kernel_launch(void* const* d_in, const int* in_sizes, int n_in,
                              void* d_out, int out_size) {
    const float* x = (const float*)d_in[0];   // [n]
    const float* W = (const float*)d_in[1];   // [n, n] row-major
    float*       y = (float*)d_out;           // [n]

    const int n = in_sizes[0];                // 8192 (even)

    tril_mv_kernel<<<n / 2, NTHREADS>>>(x, W, y, n);
}

// round 7
// speedup vs baseline: 1.2188x; 1.2188x over previous
#include <cuda_runtime.h>
#include <cstdint>

// Lower-triangular matvec: y[i] = sum_{j<=i} W[i,j] * x[j]
// n = 8192, W row-major fp32 (lower triangle = 128 MB, streamed once).
//
// R7: pair-block layout (block b -> rows b and n-1-b; every block moves
// exactly n+1 floats). W is streamed with 1D TMA bulk copies
// (cp.async.bulk ... complete_tx::bytes) into a 4-stage x 8 KB shared-memory
// pipeline: 32 KB of W in flight per block with ZERO register cost, so high
// MLP and high occupancy coexist (they fought each other in R2/R6).
// Compute: LDS.128 on staged W, __ldg float4 on x (L1-resident).

#define NTHREADS   256
#define CHUNK_F    2048                 // floats per chunk (8 KB)
#define STAGES     4

__device__ __forceinline__ float dot4(float4 w, float4 v) {
    return w.x * v.x + w.y * v.y + w.z * v.z + w.w * v.w;
}

__device__ __forceinline__ uint32_t smem_u32(const void* p) {
    return (uint32_t)__cvta_generic_to_shared(p);
}

__device__ __forceinline__ void mbar_init(uint32_t mbar, uint32_t count) {
    asm volatile("mbarrier.init.shared.b64 [%0], %1;" :: "r"(mbar), "r"(count) : "memory");
}

__device__ __forceinline__ void mbar_expect_tx(uint32_t mbar, uint32_t bytes) {
    asm volatile("mbarrier.arrive.expect_tx.shared.b64 _, [%0], %1;"
                 :: "r"(mbar), "r"(bytes) : "memory");
}

__device__ __forceinline__ void mbar_wait(uint32_t mbar, uint32_t parity) {
    asm volatile(
        "{\n\t"
        ".reg .pred P;\n\t"
        "WAIT_%=: mbarrier.try_wait.parity.acquire.cta.shared::cta.b64 P, [%0], %1, 0x989680;\n\t"
        "@P bra.uni DONE_%=;\n\t"
        "bra.uni WAIT_%=;\n\t"
        "DONE_%=:\n\t"
        "}"
        :: "r"(mbar), "r"(parity) : "memory");
}

__device__ __forceinline__ void bulk_copy_g2s(uint32_t dst_smem, const void* src,
                                              uint32_t bytes, uint32_t mbar) {
    asm volatile(
        "cp.async.bulk.shared::cluster.global.mbarrier::complete_tx::bytes "
        "[%0], [%1], %2, [%3];"
        :: "r"(dst_smem), "l"(src), "r"(bytes), "r"(mbar) : "memory");
}

__global__ __launch_bounds__(NTHREADS)
void tril_mv_kernel(const float* __restrict__ x,
                    const float* __restrict__ W,
                    float* __restrict__ y,
                    int n)
{
    __shared__ __align__(16) float buf[STAGES][CHUNK_F];   // 32 KB
    __shared__ uint64_t mbar[STAGES];
    __shared__ float red0[NTHREADS / 32];
    __shared__ float red1[NTHREADS / 32];

    const int tid = threadIdx.x;
    const int b   = blockIdx.x;
    const int r0  = b;
    const int r1  = n - 1 - b;

    const int len0 = r0 + 1;
    const int len1 = r1 + 1;
    const int nch0 = (len0 + CHUNK_F - 1) / CHUNK_F;
    const int nch1 = (len1 + CHUNK_F - 1) / CHUNK_F;
    const int NC   = nch0 + nch1;     // 5 or 6 for n=8192

    if (tid == 0) {
        #pragma unroll
        for (int s = 0; s < STAGES; s++) mbar_init(smem_u32(&mbar[s]), 1);
    }
    __syncthreads();

    // Chunk c metadata: row base, column offset, float count.
    auto chunk_meta = [&](int c, const float*& src, int& off, int& f) {
        if (c < nch0) {
            off = c * CHUNK_F;
            f   = min(CHUNK_F, len0 - off);
            src = W + (size_t)r0 * n + off;
        } else {
            off = (c - nch0) * CHUNK_F;
            f   = min(CHUNK_F, len1 - off);
            src = W + (size_t)r1 * n + off;
        }
    };

    auto issue = [&](int c) {
        const float* src; int off, f;
        chunk_meta(c, src, off, f);
        const uint32_t bytes = ((uint32_t)f * 4u + 15u) & ~15u;  // within 32KB row
        const int s = c & (STAGES - 1);
        const uint32_t m = smem_u32(&mbar[s]);
        mbar_expect_tx(m, bytes);
        bulk_copy_g2s(smem_u32(&buf[s][0]), src, bytes, m);
    };

    // Prime the pipeline.
    if (tid == 0) {
        for (int c = 0; c < STAGES && c < NC; c++) issue(c);
    }

    const float4* __restrict__ x4 = reinterpret_cast<const float4*>(x);

    float acc0 = 0.0f, acc1 = 0.0f;

    for (int c = 0; c < NC; c++) {
        const int s = c & (STAGES - 1);
        mbar_wait(smem_u32(&mbar[s]), (uint32_t)(c >> 2) & 1u);

        const float* src; int off, f;
        chunk_meta(c, src, off, f);

        const float4* b4 = reinterpret_cast<const float4*>(&buf[s][0]);
        const int m4 = f >> 2;             // <= 512
        const int xb = off >> 2;           // x float4 base

        float part = 0.0f;
        if (tid < m4)
            part += dot4(b4[tid], __ldg(x4 + xb + tid));
        if (tid + NTHREADS < m4)
            part += dot4(b4[tid + NTHREADS], __ldg(x4 + xb + tid + NTHREADS));
        const int tail = f & 3;
        if (tid < tail) {
            const int j = (m4 << 2) + tid;
            part += buf[s][j] * x[off + j];
        }

        if (c < nch0) acc0 += part; else acc1 += part;

        __syncthreads();                   // stage s fully consumed
        if (tid == 0 && c + STAGES < NC) issue(c + STAGES);
    }

    // ---- dual block reduction ----
    #pragma unroll
    for (int off = 16; off > 0; off >>= 1) {
        acc0 += __shfl_down_sync(0xffffffffu, acc0, off);
        acc1 += __shfl_down_sync(0xffffffffu, acc1, off);
    }
    const int warp = tid >> 5;
    const int lane = tid & 31;
    if (lane == 0) { red0[warp] = acc0; red1[warp] = acc1; }
    __syncthreads();

    if (warp == 0) {
        float a0 = (lane < NTHREADS / 32) ? red0[lane] : 0.0f;
        float a1 = (lane < NTHREADS / 32) ? red1[lane] : 0.0f;
        #pragma unroll
        for (int off = (NTHREADS / 64); off > 0; off >>= 1) {
            a0 += __shfl_down_sync(0xffffffffu, a0, off);
            a1 += __shfl_down_sync(0xffffffffu, a1, off);
        }
        if (lane == 0) { y[r0] = a0; y[r1] = a1; }
    }
}

extern "C" void kernel_launch(void* const* d_in, const int* in_sizes, int n_in,
                              void* d_out, int out_size) {
    const float* x = (const float*)d_in[0];   // [n]
    const float* W = (const float*)d_in[1];   // [n, n] row-major
    float*       y = (float*)d_out;           // [n]

    const int n = in_sizes[0];                // 8192 (even)

    tril_mv_kernel<<<n / 2, NTHREADS>>>(x, W, y, n);
}

// round 8
// speedup vs baseline: 1.2613x; 1.0348x over previous
#include <cuda_runtime.h>
#include <cstdint>

// Lower-triangular matvec: y[i] = sum_{j<=i} W[i,j] * x[j]
// n = 8192, W row-major fp32 (lower triangle = 128 MB, streamed once).
//
// R8: pair-block layout (block b -> rows b and n-1-b; exactly n+1 floats per
// block -> perfect balance). Each block copies BOTH rows' float4 data into
// shared memory with one massive cp.async burst (issue-all / wait-all / one
// barrier), then consumes from smem. In-flight W bytes live in smem (zero
// register cost); block-phase interleaving across ~6 resident blocks/SM keeps
// DRAM continuously fed, fixing the drain-refill duty-cycle that capped
// register-batched versions at ~62% DRAM.

#define NTHREADS 256
#define BUF_F4   2048   // float4 slots: (len0>>2)+(len1>>2) <= (n+1)/4 = 2048

__device__ __forceinline__ float dot4(float4 w, float4 v) {
    return w.x * v.x + w.y * v.y + w.z * v.z + w.w * v.w;
}

__device__ __forceinline__ void cp_async16(void* dst_smem, const void* src_gmem) {
    uint32_t d = (uint32_t)__cvta_generic_to_shared(dst_smem);
    asm volatile("cp.async.cg.shared.global [%0], [%1], 16;"
                 :: "r"(d), "l"(src_gmem) : "memory");
}

__device__ __forceinline__ void cp_async_commit_wait_all() {
    asm volatile("cp.async.commit_group;" ::: "memory");
    asm volatile("cp.async.wait_group 0;" ::: "memory");
}

__global__ __launch_bounds__(NTHREADS)
void tril_mv_kernel(const float* __restrict__ x,
                    const float* __restrict__ W,
                    float* __restrict__ y,
                    int n)
{
    __shared__ __align__(16) float4 buf4[BUF_F4];          // 32 KB
    __shared__ float red0[NTHREADS / 32];
    __shared__ float red1[NTHREADS / 32];

    const int tid = threadIdx.x;
    const int b   = blockIdx.x;
    const int r0  = b;
    const int r1  = n - 1 - b;

    const int len0 = r0 + 1;
    const int len1 = r1 + 1;
    const int m0   = len0 >> 2;            // full float4s in row 0
    const int m1   = len1 >> 2;            // full float4s in row 1

    const float4* __restrict__ W40 =
        reinterpret_cast<const float4*>(W + (size_t)r0 * n);
    const float4* __restrict__ W41 =
        reinterpret_cast<const float4*>(W + (size_t)r1 * n);
    const float4* __restrict__ x4 = reinterpret_cast<const float4*>(x);

    // ---- issue the whole block's W as one cp.async burst ----
    #pragma unroll 4
    for (int k = tid; k < m0; k += NTHREADS)
        cp_async16(&buf4[k], W40 + k);
    #pragma unroll 4
    for (int k = tid; k < m1; k += NTHREADS)
        cp_async16(&buf4[m0 + k], W41 + k);
    cp_async_commit_wait_all();
    __syncthreads();

    // ---- consume from smem ----
    float acc0 = 0.0f, acc1 = 0.0f;

    {
        float s0 = 0.f, s1 = 0.f, s2 = 0.f, s3 = 0.f;
        int k = tid;
        for (; k + 3 * NTHREADS < m0; k += 4 * NTHREADS) {
            s0 += dot4(buf4[k],                __ldg(x4 + k));
            s1 += dot4(buf4[k + NTHREADS],     __ldg(x4 + k + NTHREADS));
            s2 += dot4(buf4[k + 2 * NTHREADS], __ldg(x4 + k + 2 * NTHREADS));
            s3 += dot4(buf4[k + 3 * NTHREADS], __ldg(x4 + k + 3 * NTHREADS));
        }
        #pragma unroll 1
        for (; k < m0; k += NTHREADS)
            s0 += dot4(buf4[k], __ldg(x4 + k));
        acc0 = (s0 + s1) + (s2 + s3);
        const int tail = len0 & 3;
        if (tid < tail) {
            const int j = (m0 << 2) + tid;
            acc0 += W[(size_t)r0 * n + j] * x[j];
        }
    }
    {
        float s0 = 0.f, s1 = 0.f, s2 = 0.f, s3 = 0.f;
        int k = tid;
        for (; k + 3 * NTHREADS < m1; k += 4 * NTHREADS) {
            s0 += dot4(buf4[m0 + k],                __ldg(x4 + k));
            s1 += dot4(buf4[m0 + k + NTHREADS],     __ldg(x4 + k + NTHREADS));
            s2 += dot4(buf4[m0 + k + 2 * NTHREADS], __ldg(x4 + k + 2 * NTHREADS));
            s3 += dot4(buf4[m0 + k + 3 * NTHREADS], __ldg(x4 + k + 3 * NTHREADS));
        }
        #pragma unroll 1
        for (; k < m1; k += NTHREADS)
            s0 += dot4(buf4[m0 + k], __ldg(x4 + k));
        acc1 = (s0 + s1) + (s2 + s3);
        const int tail = len1 & 3;
        if (tid < tail) {
            const int j = (m1 << 2) + tid;
            acc1 += W[(size_t)r1 * n + j] * x[j];
        }
    }

    // ---- dual block reduction ----
    #pragma unroll
    for (int off = 16; off > 0; off >>= 1) {
        acc0 += __shfl_down_sync(0xffffffffu, acc0, off);
        acc1 += __shfl_down_sync(0xffffffffu, acc1, off);
    }
    const int warp = tid >> 5;
    const int lane = tid & 31;
    if (lane == 0) { red0[warp] = acc0; red1[warp] = acc1; }
    __syncthreads();

    if (warp == 0) {
        float a0 = (lane < NTHREADS / 32) ? red0[lane] : 0.0f;
        float a1 = (lane < NTHREADS / 32) ? red1[lane] : 0.0f;
        #pragma unroll
        for (int off = (NTHREADS / 64); off > 0; off >>= 1) {
            a0 += __shfl_down_sync(0xffffffffu, a0, off);
            a1 += __shfl_down_sync(0xffffffffu, a1, off);
        }
        if (lane == 0) { y[r0] = a0; y[r1] = a1; }
    }
}

extern "C" void kernel_launch(void* const* d_in, const int* in_sizes, int n_in,
                              void* d_out, int out_size) {
    const float* x = (const float*)d_in[0];   // [n]
    const float* W = (const float*)d_in[1];   // [n, n] row-major
    float*       y = (float*)d_out;           // [n]

    const int n = in_sizes[0];                // 8192 (even)

    tril_mv_kernel<<<n / 2, NTHREADS>>>(x, W, y, n);
}